// round 8
// baseline (speedup 1.0000x reference)
#include <cuda_runtime.h>
#include <cstdint>

#define B 64
#define P 8732
#define C 81
#define O 32
#define RPB 128          // rows per loss block (B*P = 558848 = 128*4366)
#define NSLICE 8
#define CHUNK 1092       // ceil(P/NSLICE)

#define NEG_INF (__int_as_float(0xff800000))

// ---------------- scratch (device globals; no allocation anywhere) ----------
__device__ unsigned long long g_obj_slice[B * NSLICE * O]; // (ov_bits<<32)|~p
__device__ int   g_match[B * P];                 // packed (obj<<8)|tc per prior
__device__ float g_mined[B * P];                 // bg_loss (neg) / -inf (pos)
__device__ int   g_num_pos[B];
__device__ float g_neg_sum[B];
__device__ float g_pos_ce;
__device__ float g_sl1;
__device__ int   g_done;

// ---------------- helpers ----------------------------------------------------
__device__ __forceinline__ unsigned okey(float f) {
    unsigned u = __float_as_uint(f);
    return (u & 0x80000000u) ? ~u : (u | 0x80000000u);
}
__device__ __forceinline__ float fromkey(unsigned k) {
    unsigned u = (k & 0x80000000u) ? (k & 0x7FFFFFFFu) : ~k;
    return __uint_as_float(u);
}
__device__ __forceinline__ float smoothl1(float d) {
    float a = fabsf(d);
    return (a < 1.0f) ? 0.5f * a * a : a - 0.5f;
}
__device__ __forceinline__ float iou_fast(float4 bx, float barea,
                                          float px0, float py0, float px1, float py1,
                                          float parea) {
    float lx = fmaxf(bx.x, px0), ly = fmaxf(bx.y, py0);
    float hx = fminf(bx.z, px1), hy = fminf(bx.w, py1);
    float w = fmaxf(hx - lx, 0.0f), h = fmaxf(hy - ly, 0.0f);
    float inter = w * h;
    return __fdividef(inter, barea + parea - inter);   // MUFU.RCP + FMUL
}

// ---------------- K1: matching, branch-free integer-max keys -----------------
__global__ void __launch_bounds__(512, 3) match_kernel(
        const float* __restrict__ boxes,
        const int*   __restrict__ labels,
        const float* __restrict__ priors) {
    int slice = blockIdx.x;          // 0..7
    int b = blockIdx.y;
    int tid = threadIdx.x;
    int wid = tid >> 5;              // 0..15
    int lane = tid & 31;
    __shared__ float4 sbox[O];
    __shared__ float  sarea[O];
    __shared__ int    slab[O];
    if (tid < O) {
        float4 bx = ((const float4*)boxes)[b * O + tid];
        sbox[tid] = bx;
        sarea[tid] = (bx.z - bx.x) * (bx.w - bx.y);
        slab[tid] = labels[b * O + tid];
    }
    if (slice == 0 && b == 0) {      // init accumulators for downstream launches
        if (tid < B) { g_num_pos[tid] = 0; g_neg_sum[tid] = 0.0f; }
        if (tid == 0) { g_pos_ce = 0.0f; g_sl1 = 0.0f; g_done = 0; }
    }
    __syncthreads();

    int pstart = slice * CHUNK;
    int pend = min(P, pstart + CHUNK);

    // ---- phase A: per-prior argmax over 32 objects (LOP3+IMNMX, no preds) ---
    for (int p = pstart + tid; p < pend; p += 512) {
        float4 pr = ((const float4*)priors)[p];
        float px0 = pr.x - 0.5f * pr.z, py0 = pr.y - 0.5f * pr.w;
        float px1 = pr.x + 0.5f * pr.z, py1 = pr.y + 0.5f * pr.w;
        float parea = pr.z * pr.w;
        unsigned best = 0u;
#pragma unroll
        for (int o = 0; o < O; o++) {
            float ov = iou_fast(sbox[o], sarea[o], px0, py0, px1, py1, parea);
            // mask 5 low mantissa bits, embed (31-o): lowest o wins ties
            unsigned key = (__float_as_uint(ov) & 0xFFFFFFE0u) | (unsigned)(31 - o);
            best = max(best, key);
        }
        int bo = 31 - (int)(best & 31u);
        float bov = __uint_as_float(best & 0xFFFFFFE0u);
        int tc = (bov < 0.5f) ? 0 : slab[bo];
        g_match[b * P + p] = (bo << 8) | tc;
    }

    // ---- phase B: warp per object (2 objects per warp), key embeds iter -----
    for (int rep = 0; rep < 2; rep++) {
        int obj = wid + rep * 16;
        float4 bx = sbox[obj];
        float barea = sarea[obj];
        unsigned best = 0u;
        int i = 0;
        for (int p = pstart + lane; p < pend; p += 32, i++) {
            float4 pr = ((const float4*)priors)[p];
            float px0 = pr.x - 0.5f * pr.z, py0 = pr.y - 0.5f * pr.w;
            float px1 = pr.x + 0.5f * pr.z, py1 = pr.y + 0.5f * pr.w;
            float parea = pr.z * pr.w;
            float ov = iou_fast(bx, barea, px0, py0, px1, py1, parea);
            // mask 7 low mantissa bits, embed (127-i): smaller i (=smaller p) wins
            unsigned key = (__float_as_uint(ov) & 0xFFFFFF80u) | (unsigned)(127 - i);
            best = max(best, key);
        }
        int ib = 127 - (int)(best & 127u);
        unsigned pbest = (unsigned)(pstart + lane + (ib << 5));
        unsigned long long packed =
            ((unsigned long long)(best & 0xFFFFFF80u) << 32) |
            (0xFFFFFFFFu - pbest);                     // lower p wins ties
#pragma unroll
        for (int off = 16; off; off >>= 1) {
            unsigned long long v = __shfl_xor_sync(0xFFFFFFFFu, packed, off);
            if (v > packed) packed = v;
        }
        if (lane == 0)
            g_obj_slice[(b * NSLICE + slice) * O + obj] = packed;
    }
}

// ---------------- K2: smem-tiled losses, 4 threads per row -------------------
__global__ void __launch_bounds__(512) loss_kernel(const float* __restrict__ locs,
                            const float* __restrict__ scores,
                            const int*   __restrict__ labels,
                            const float* __restrict__ boxes,
                            const float* __restrict__ priors) {
    __shared__ float sm[RPB * C];                  // 41472 bytes
    __shared__ unsigned spriorF[2][O];
    __shared__ int slabF[2][O];
    size_t row0 = (size_t)blockIdx.x * RPB;
    int b0 = (int)(row0 / P);

    if (threadIdx.x < 64) {                        // reduce slices -> forced priors
        int bi = threadIdx.x >> 5, o = threadIdx.x & 31;
        int bb = min(b0 + bi, B - 1);
        unsigned long long m = 0ULL;
#pragma unroll
        for (int s = 0; s < NSLICE; s++)
            m = max(m, g_obj_slice[(bb * NSLICE + s) * O + o]);
        spriorF[bi][o] = 0xFFFFFFFFu - (unsigned)(m & 0xFFFFFFFFu);
        slabF[bi][o] = labels[bb * O + o];
    }

    // stage 128 rows flat (row0 multiple of 128 -> 16B aligned)
    const float4* src = (const float4*)(scores + row0 * C);
    float4* dst = (float4*)sm;
    const int N4 = RPB * C / 4;                    // 2592
#pragma unroll 4
    for (int i = threadIdx.x; i < N4; i += 512) dst[i] = src[i];
    __syncthreads();

    int k = threadIdx.x >> 2;                      // local row
    int q = threadIdx.x & 3;                       // quarter
    const float* my = sm + k * C;
    int jstart = q * 20;

    float s0 = 0.f, s1 = 0.f, s2 = 0.f, s3 = 0.f;
#pragma unroll
    for (int jj = 0; jj < 20; jj += 4) {
        s0 += __expf(my[jstart + jj]);
        s1 += __expf(my[jstart + jj + 1]);
        s2 += __expf(my[jstart + jj + 2]);
        s3 += __expf(my[jstart + jj + 3]);
    }
    float sum = (s0 + s1) + (s2 + s3);
    if (q == 3) sum += __expf(my[80]);
    sum += __shfl_xor_sync(0xFFFFFFFFu, sum, 1);   // quarters live in same warp
    sum += __shfl_xor_sync(0xFFFFFFFFu, sum, 2);
    float lse = __logf(sum);

    if (q == 0) {
        int r = (int)row0 + k;
        int b = r / P;
        int p = r - b * P;
        int bi = b - b0;

        int mm = g_match[r];
        int tc = mm & 0xFF;
        int obj = mm >> 8;
#pragma unroll
        for (int o = 0; o < O; o++) {              // ascending: last (highest o) wins
            if (spriorF[bi][o] == (unsigned)p) { tc = slabF[bi][o]; obj = o; }
        }

        float mined;
        if (tc > 0) {
            atomicAdd(&g_pos_ce, lse - my[tc]);
            atomicAdd(&g_num_pos[b], 1);
            float4 bx = ((const float4*)boxes)[b * O + obj];
            float4 pr = ((const float4*)priors)[p];
            float cx = 0.5f * (bx.x + bx.z), cy = 0.5f * (bx.y + bx.w);
            float w = bx.z - bx.x, h = bx.w - bx.y;
            float t0 = (cx - pr.x) * 10.0f / pr.z;
            float t1 = (cy - pr.y) * 10.0f / pr.w;
            float t2 = __logf(w / pr.z) * 5.0f;
            float t3 = __logf(h / pr.w) * 5.0f;
            float4 pl = ((const float4*)locs)[r];
            float sl = smoothl1(pl.x - t0) + smoothl1(pl.y - t1) +
                       smoothl1(pl.z - t2) + smoothl1(pl.w - t3);
            atomicAdd(&g_sl1, sl);
            mined = NEG_INF;
        } else {
            mined = lse - my[0];
        }
        g_mined[r] = mined;
    }
}

// ---------------- K3: per-batch radix-select top-K + fused finalize ----------
__global__ void __launch_bounds__(512) select_kernel(float* __restrict__ out) {
    int b = blockIdx.x;
    int tid = threadIdx.x;
    const float* mined = g_mined + b * P;

    __shared__ int hist[256];
    __shared__ int ssum[256];
    __shared__ int wtot[8];
    __shared__ unsigned sprefix;
    __shared__ int sK;
    __shared__ float swsum[16];
    __shared__ int slastf;

    int np = g_num_pos[b];
    int K = min(3 * np, P - np);
    float result = 0.0f;

    if (K > 0) {
        if (tid == 0) { sprefix = 0u; sK = K; }
        __syncthreads();
        for (int shift = 24; shift >= 0; shift -= 8) {
            if (tid < 256) hist[tid] = 0;
            __syncthreads();
            unsigned prefix = sprefix;
            int Kr = sK;
            for (int p = tid; p < P; p += 512) {
                unsigned k = okey(mined[p]);
                if (shift == 24 || (k >> (shift + 8)) == prefix)
                    atomicAdd(&hist[(k >> shift) & 255u], 1);
            }
            __syncthreads();
            int v = 0;
            int w = tid >> 5, l = tid & 31;
            if (tid < 256) {                       // warp-level suffix scan
                v = hist[tid];
#pragma unroll
                for (int off = 1; off < 32; off <<= 1) {
                    int u = __shfl_down_sync(0xFFFFFFFFu, v, off);
                    if (l + off < 32) v += u;
                }
                if (l == 0) wtot[w] = v;
            }
            __syncthreads();
            if (tid < 256) {
                int add = 0;
#pragma unroll
                for (int g = 1; g < 8; g++) if (w + g < 8) add += wtot[w + g];
                ssum[tid] = v + add;
            }
            __syncthreads();
            if (tid < 256) {
                int mine = ssum[tid];
                int nxt = (tid < 255) ? ssum[tid + 1] : 0;
                if (mine >= Kr && nxt < Kr) {      // unique tid
                    sprefix = (prefix << 8) | (unsigned)tid;
                    sK = Kr - nxt;
                }
            }
            __syncthreads();
        }
        unsigned T = sprefix;
        int rr = sK;
        float Tval = fromkey(T);

        float sum = 0.0f;
        for (int p = tid; p < P; p += 512) {
            float v2 = mined[p];
            if (okey(v2) > T) sum += v2;
        }
#pragma unroll
        for (int off = 16; off; off >>= 1) sum += __shfl_xor_sync(0xFFFFFFFFu, sum, off);
        if ((tid & 31) == 0) swsum[tid >> 5] = sum;
        __syncthreads();
        if (tid == 0) {
            float tot = 0.0f;
#pragma unroll
            for (int i = 0; i < 16; i++) tot += swsum[i];
            result = tot + (float)rr * Tval;
        }
    }

    if (tid == 0) {
        g_neg_sum[b] = result;
        __threadfence();
        int d = atomicAdd(&g_done, 1);
        slastf = (d == B - 1);
    }
    __syncthreads();

    if (slastf) {                                  // last block finalizes
        __threadfence();
        float ns = 0.0f, npv = 0.0f;
        if (tid < B) {
            ns = *(volatile float*)&g_neg_sum[tid];
            npv = (float)*(volatile int*)&g_num_pos[tid];
        }
#pragma unroll
        for (int off = 16; off; off >>= 1) {
            ns += __shfl_xor_sync(0xFFFFFFFFu, ns, off);
            npv += __shfl_xor_sync(0xFFFFFFFFu, npv, off);
        }
        __shared__ float a2[2], c2[2];
        if (tid < B && (tid & 31) == 0) { a2[tid >> 5] = ns; c2[tid >> 5] = npv; }
        __syncthreads();
        if (tid == 0) {
            float totns = a2[0] + a2[1];
            float n = c2[0] + c2[1];
            out[0] = (g_pos_ce + totns) / n;
            out[1] = g_sl1 / n;
        }
    }
}

// ---------------- launch ------------------------------------------------------
extern "C" void kernel_launch(void* const* d_in, const int* in_sizes, int n_in,
                              void* d_out, int out_size) {
    const float* locs   = (const float*)d_in[0];   // [B,P,4]
    const float* scores = (const float*)d_in[1];   // [B,P,C]
    const float* boxes  = (const float*)d_in[2];   // [B,O,4] xy
    const int*   labels = (const int*)  d_in[3];   // [B,O]
    const float* priors = (const float*)d_in[4];   // [P,4] cxcywh
    float* out = (float*)d_out;

    match_kernel<<<dim3(NSLICE, B), 512>>>(boxes, labels, priors);
    loss_kernel<<<(B * P) / RPB, 512>>>(locs, scores, labels, boxes, priors);
    select_kernel<<<B, 512>>>(out);
}

// round 9
// speedup vs baseline: 1.8442x; 1.8442x over previous
#include <cuda_runtime.h>
#include <cstdint>

#define B 64
#define P 8732
#define C 81
#define O 32
#define RPB 128            // rows per loss block (B*P = 558848 = 128*4366)
#define NSLICE 16          // match blocks per batch item
#define BATCH_STRIDE (NSLICE * 16 * 32)   // 8192 priors per warp-sweep

#define NEG_INF (__int_as_float(0xff800000))

// ---------------- scratch (device globals; no allocation anywhere) ----------
__device__ unsigned long long g_obj_slice[B * NSLICE * O]; // (ov_bits<<32)|~p
__device__ int   g_match[B * P];                 // packed (obj<<8)|tc per prior
__device__ float g_mined[B * P];                 // bg_loss (neg) / -inf (pos)
__device__ int   g_num_pos[B];
__device__ float g_neg_sum[B];
__device__ float g_pos_ce;
__device__ float g_sl1;
__device__ int   g_done;

// ---------------- helpers ----------------------------------------------------
__device__ __forceinline__ unsigned okey(float f) {
    unsigned u = __float_as_uint(f);
    return (u & 0x80000000u) ? ~u : (u | 0x80000000u);
}
__device__ __forceinline__ float fromkey(unsigned k) {
    unsigned u = (k & 0x80000000u) ? (k & 0x7FFFFFFFu) : ~k;
    return __uint_as_float(u);
}
__device__ __forceinline__ float smoothl1(float d) {
    float a = fabsf(d);
    return (a < 1.0f) ? 0.5f * a * a : a - 0.5f;
}

// ---------------- K1: fused matching, single IoU pass ------------------------
// Each warp owns 32 priors per batch sweep. For each object o:
//   - per-prior argmax accumulates in-thread (keyA)
//   - per-object max across the warp via one REDUX.MAX; lane o keeps it (keyB)
__global__ void __launch_bounds__(512, 2) match_kernel(
        const float* __restrict__ boxes,
        const int*   __restrict__ labels,
        const float* __restrict__ priors) {
    int blk = blockIdx.x;            // 0..NSLICE-1
    int b = blockIdx.y;
    int tid = threadIdx.x;
    int wid = tid >> 5;              // 0..15
    int lane = tid & 31;
    __shared__ float4 sbox[O];
    __shared__ float  sarea[O];
    __shared__ int    slab[O];
    __shared__ unsigned swkey[16][O];    // per-warp per-object best key
    if (tid < O) {
        float4 bx = ((const float4*)boxes)[b * O + tid];
        sbox[tid] = bx;
        sarea[tid] = (bx.z - bx.x) * (bx.w - bx.y);
        slab[tid] = labels[b * O + tid];
    }
    if (blk == 0 && b == 0) {        // init accumulators for downstream launches
        if (tid < B) { g_num_pos[tid] = 0; g_neg_sum[tid] = 0.0f; }
        if (tid == 0) { g_pos_ce = 0.0f; g_sl1 = 0.0f; g_done = 0; }
    }
    __syncthreads();

    int gwarp = blk * 16 + wid;      // 0..255 within this batch item
    unsigned runB = 0u;              // lane L holds object L's running best key

    for (int batch = 0; batch < 2; batch++) {
        int pbase = batch * BATCH_STRIDE + gwarp * 32;
        if (pbase >= P) break;
        int p = pbase + lane;
        bool valid = (p < P);
        int pc = valid ? p : (P - 1);

        float4 pr = ((const float4*)priors)[pc];       // cxcywh
        float px0 = pr.x - 0.5f * pr.z, py0 = pr.y - 0.5f * pr.w;
        float px1 = pr.x + 0.5f * pr.z, py1 = pr.y + 0.5f * pr.w;
        float parea = pr.z * pr.w;

        unsigned bestA = 0u;
#pragma unroll
        for (int o = 0; o < O; o++) {
            float4 bx = sbox[o];
            float lx = fmaxf(bx.x, px0), ly = fmaxf(bx.y, py0);
            float hx = fminf(bx.z, px1), hy = fminf(bx.w, py1);
            float w = fmaxf(hx - lx, 0.0f), h = fmaxf(hy - ly, 0.0f);
            float inter = w * h;
            float ov = __fdividef(inter, sarea[o] + parea - inter);
            unsigned ob = __float_as_uint(ov);
            // per-prior argmax: mask 5 bits, embed (31-o) -> lowest o wins ties
            bestA = max(bestA, (ob & 0xFFFFFFE0u) | (unsigned)(31 - o));
            // per-object max: mask 7 bits, embed (3-batch)<<5 | (31-lane)
            unsigned keyB = valid
                ? ((ob & 0xFFFFFF80u) | (unsigned)((3 - batch) << 5) | (unsigned)(31 - lane))
                : 0u;
            unsigned m = __reduce_max_sync(0xFFFFFFFFu, keyB);
            if (lane == o) runB = max(runB, m);
        }
        if (valid) {
            int bo = 31 - (int)(bestA & 31u);
            float bov = __uint_as_float(bestA & 0xFFFFFFE0u);
            int tc = (bov < 0.5f) ? 0 : slab[bo];
            g_match[b * P + p] = (bo << 8) | tc;
        }
    }

    swkey[wid][lane] = runB;         // lane L = object L
    __syncthreads();

    if (tid < O) {                   // thread o: combine 16 warps
        int o = tid;
        unsigned long long best = 0ULL;
#pragma unroll
        for (int w = 0; w < 16; w++) {
            unsigned k = swkey[w][o];
            int batch = 3 - (int)((k >> 5) & 3u);
            int ln = 31 - (int)(k & 31u);
            unsigned p = (unsigned)(batch * BATCH_STRIDE + (blk * 16 + w) * 32 + ln);
            unsigned long long cand =
                ((unsigned long long)(k & 0xFFFFFF80u) << 32) | (0xFFFFFFFFu - p);
            if (cand > best) best = cand;
        }
        g_obj_slice[(b * NSLICE + blk) * O + o] = best;
    }
}

// ---------------- K2: smem-tiled losses, 4 threads per row -------------------
__global__ void __launch_bounds__(512) loss_kernel(const float* __restrict__ locs,
                            const float* __restrict__ scores,
                            const int*   __restrict__ labels,
                            const float* __restrict__ boxes,
                            const float* __restrict__ priors) {
    __shared__ float sm[RPB * C];                  // 41472 bytes
    __shared__ unsigned spriorF[2][O];
    __shared__ int slabF[2][O];
    size_t row0 = (size_t)blockIdx.x * RPB;
    int b0 = (int)(row0 / P);

    if (threadIdx.x < 64) {                        // reduce slices -> forced priors
        int bi = threadIdx.x >> 5, o = threadIdx.x & 31;
        int bb = min(b0 + bi, B - 1);
        unsigned long long m = 0ULL;
#pragma unroll
        for (int s = 0; s < NSLICE; s++)
            m = max(m, g_obj_slice[(bb * NSLICE + s) * O + o]);
        spriorF[bi][o] = 0xFFFFFFFFu - (unsigned)(m & 0xFFFFFFFFu);
        slabF[bi][o] = labels[bb * O + o];
    }

    // stage 128 rows flat (row0 multiple of 128 -> 16B aligned)
    const float4* src = (const float4*)(scores + row0 * C);
    float4* dst = (float4*)sm;
    const int N4 = RPB * C / 4;                    // 2592
#pragma unroll 4
    for (int i = threadIdx.x; i < N4; i += 512) dst[i] = src[i];
    __syncthreads();

    int k = threadIdx.x >> 2;                      // local row
    int q = threadIdx.x & 3;                       // quarter
    const float* my = sm + k * C;
    int jstart = q * 20;

    float s0 = 0.f, s1 = 0.f, s2 = 0.f, s3 = 0.f;
#pragma unroll
    for (int jj = 0; jj < 20; jj += 4) {
        s0 += __expf(my[jstart + jj]);
        s1 += __expf(my[jstart + jj + 1]);
        s2 += __expf(my[jstart + jj + 2]);
        s3 += __expf(my[jstart + jj + 3]);
    }
    float sum = (s0 + s1) + (s2 + s3);
    if (q == 3) sum += __expf(my[80]);
    sum += __shfl_xor_sync(0xFFFFFFFFu, sum, 1);   // quarters live in same warp
    sum += __shfl_xor_sync(0xFFFFFFFFu, sum, 2);
    float lse = __logf(sum);

    if (q == 0) {
        int r = (int)row0 + k;
        int b = r / P;
        int p = r - b * P;
        int bi = b - b0;

        int mm = g_match[r];
        int tc = mm & 0xFF;
        int obj = mm >> 8;
#pragma unroll
        for (int o = 0; o < O; o++) {              // ascending: last (highest o) wins
            if (spriorF[bi][o] == (unsigned)p) { tc = slabF[bi][o]; obj = o; }
        }

        float mined;
        if (tc > 0) {
            atomicAdd(&g_pos_ce, lse - my[tc]);
            atomicAdd(&g_num_pos[b], 1);
            float4 bx = ((const float4*)boxes)[b * O + obj];
            float4 pr = ((const float4*)priors)[p];
            float cx = 0.5f * (bx.x + bx.z), cy = 0.5f * (bx.y + bx.w);
            float w = bx.z - bx.x, h = bx.w - bx.y;
            float t0 = (cx - pr.x) * 10.0f / pr.z;
            float t1 = (cy - pr.y) * 10.0f / pr.w;
            float t2 = __logf(w / pr.z) * 5.0f;
            float t3 = __logf(h / pr.w) * 5.0f;
            float4 pl = ((const float4*)locs)[r];
            float sl = smoothl1(pl.x - t0) + smoothl1(pl.y - t1) +
                       smoothl1(pl.z - t2) + smoothl1(pl.w - t3);
            atomicAdd(&g_sl1, sl);
            mined = NEG_INF;
        } else {
            mined = lse - my[0];
        }
        g_mined[r] = mined;
    }
}

// ---------------- K3: per-batch radix-select top-K + fused finalize ----------
__global__ void __launch_bounds__(512) select_kernel(float* __restrict__ out) {
    int b = blockIdx.x;
    int tid = threadIdx.x;
    const float* mined = g_mined + b * P;

    __shared__ int hist[256];
    __shared__ int ssum[256];
    __shared__ int wtot[8];
    __shared__ unsigned sprefix;
    __shared__ int sK;
    __shared__ float swsum[16];
    __shared__ int slastf;

    int np = g_num_pos[b];
    int K = min(3 * np, P - np);
    float result = 0.0f;

    if (K > 0) {
        if (tid == 0) { sprefix = 0u; sK = K; }
        __syncthreads();
        for (int shift = 24; shift >= 0; shift -= 8) {
            if (tid < 256) hist[tid] = 0;
            __syncthreads();
            unsigned prefix = sprefix;
            int Kr = sK;
            for (int p = tid; p < P; p += 512) {
                unsigned k = okey(mined[p]);
                if (shift == 24 || (k >> (shift + 8)) == prefix)
                    atomicAdd(&hist[(k >> shift) & 255u], 1);
            }
            __syncthreads();
            int v = 0;
            int w = tid >> 5, l = tid & 31;
            if (tid < 256) {                       // warp-level suffix scan
                v = hist[tid];
#pragma unroll
                for (int off = 1; off < 32; off <<= 1) {
                    int u = __shfl_down_sync(0xFFFFFFFFu, v, off);
                    if (l + off < 32) v += u;
                }
                if (l == 0) wtot[w] = v;
            }
            __syncthreads();
            if (tid < 256) {
                int add = 0;
#pragma unroll
                for (int g = 1; g < 8; g++) if (w + g < 8) add += wtot[w + g];
                ssum[tid] = v + add;
            }
            __syncthreads();
            if (tid < 256) {
                int mine = ssum[tid];
                int nxt = (tid < 255) ? ssum[tid + 1] : 0;
                if (mine >= Kr && nxt < Kr) {      // unique tid
                    sprefix = (prefix << 8) | (unsigned)tid;
                    sK = Kr - nxt;
                }
            }
            __syncthreads();
        }
        unsigned T = sprefix;
        int rr = sK;
        float Tval = fromkey(T);

        float sum = 0.0f;
        for (int p = tid; p < P; p += 512) {
            float v2 = mined[p];
            if (okey(v2) > T) sum += v2;
        }
#pragma unroll
        for (int off = 16; off; off >>= 1) sum += __shfl_xor_sync(0xFFFFFFFFu, sum, off);
        if ((tid & 31) == 0) swsum[tid >> 5] = sum;
        __syncthreads();
        if (tid == 0) {
            float tot = 0.0f;
#pragma unroll
            for (int i = 0; i < 16; i++) tot += swsum[i];
            result = tot + (float)rr * Tval;
        }
    }

    if (tid == 0) {
        g_neg_sum[b] = result;
        __threadfence();
        int d = atomicAdd(&g_done, 1);
        slastf = (d == B - 1);
    }
    __syncthreads();

    if (slastf) {                                  // last block finalizes
        __threadfence();
        float ns = 0.0f, npv = 0.0f;
        if (tid < B) {
            ns = *(volatile float*)&g_neg_sum[tid];
            npv = (float)*(volatile int*)&g_num_pos[tid];
        }
#pragma unroll
        for (int off = 16; off; off >>= 1) {
            ns += __shfl_xor_sync(0xFFFFFFFFu, ns, off);
            npv += __shfl_xor_sync(0xFFFFFFFFu, npv, off);
        }
        __shared__ float a2[2], c2[2];
        if (tid < B && (tid & 31) == 0) { a2[tid >> 5] = ns; c2[tid >> 5] = npv; }
        __syncthreads();
        if (tid == 0) {
            float totns = a2[0] + a2[1];
            float n = c2[0] + c2[1];
            out[0] = (g_pos_ce + totns) / n;
            out[1] = g_sl1 / n;
        }
    }
}

// ---------------- launch ------------------------------------------------------
extern "C" void kernel_launch(void* const* d_in, const int* in_sizes, int n_in,
                              void* d_out, int out_size) {
    const float* locs   = (const float*)d_in[0];   // [B,P,4]
    const float* scores = (const float*)d_in[1];   // [B,P,C]
    const float* boxes  = (const float*)d_in[2];   // [B,O,4] xy
    const int*   labels = (const int*)  d_in[3];   // [B,O]
    const float* priors = (const float*)d_in[4];   // [P,4] cxcywh
    float* out = (float*)d_out;

    match_kernel<<<dim3(NSLICE, B), 512>>>(boxes, labels, priors);
    loss_kernel<<<(B * P) / RPB, 512>>>(locs, scores, labels, boxes, priors);
    select_kernel<<<B, 512>>>(out);
}

// round 11
// speedup vs baseline: 1.8832x; 1.0211x over previous
#include <cuda_runtime.h>
#include <cstdint>

#define B 64
#define P 8732
#define C 81
#define O 32
#define RPB 128            // rows per loss block (B*P = 558848 = 128*4366)
#define NSLICE 16          // match blocks per batch item
#define BATCH_STRIDE (NSLICE * 16 * 32)   // 8192 priors per warp-sweep

#define NEG_INF (__int_as_float(0xff800000))

// ---------------- scratch (device globals; no allocation anywhere) ----------
__device__ unsigned long long g_obj_slice[B * NSLICE * O]; // (ov_bits<<32)|~p
__device__ int   g_match[B * P];                 // packed (obj<<8)|tc per prior
__device__ float g_mined[B * P];                 // bg_loss (neg) / -inf (pos)
__device__ int   g_num_pos[B];
__device__ float g_neg_sum[B];
__device__ int   g_row_done[B];
__device__ float g_pos_ce;
__device__ float g_sl1;
__device__ int   g_done;

// ---------------- helpers ----------------------------------------------------
__device__ __forceinline__ unsigned okey(float f) {
    unsigned u = __float_as_uint(f);
    return (u & 0x80000000u) ? ~u : (u | 0x80000000u);
}
__device__ __forceinline__ float fromkey(unsigned k) {
    unsigned u = (k & 0x80000000u) ? (k & 0x7FFFFFFFu) : ~k;
    return __uint_as_float(u);
}
__device__ __forceinline__ float smoothl1(float d) {
    float a = fabsf(d);
    return (a < 1.0f) ? 0.5f * a * a : a - 0.5f;
}

// ---------------- K1: fused matching, single IoU pass ------------------------
__global__ void __launch_bounds__(512, 2) match_kernel(
        const float* __restrict__ boxes,
        const int*   __restrict__ labels,
        const float* __restrict__ priors) {
    int blk = blockIdx.x;            // 0..NSLICE-1
    int b = blockIdx.y;
    int tid = threadIdx.x;
    int wid = tid >> 5;              // 0..15
    int lane = tid & 31;
    __shared__ float4 sbox[O];
    __shared__ float  sarea[O];
    __shared__ int    slab[O];
    __shared__ unsigned swkey[16][O];    // per-warp per-object best key
    if (tid < O) {
        float4 bx = ((const float4*)boxes)[b * O + tid];
        sbox[tid] = bx;
        sarea[tid] = (bx.z - bx.x) * (bx.w - bx.y);
        slab[tid] = labels[b * O + tid];
    }
    if (blk == 0 && b == 0) {        // init accumulators for downstream launches
        if (tid < B) { g_num_pos[tid] = 0; g_neg_sum[tid] = 0.0f; g_row_done[tid] = 0; }
        if (tid == 0) { g_pos_ce = 0.0f; g_sl1 = 0.0f; g_done = 0; }
    }
    __syncthreads();

    int gwarp = blk * 16 + wid;      // 0..255 within this batch item
    unsigned runB = 0u;              // lane L holds object L's running best key

    for (int batch = 0; batch < 2; batch++) {
        int pbase = batch * BATCH_STRIDE + gwarp * 32;
        if (pbase >= P) break;
        int p = pbase + lane;
        bool valid = (p < P);
        int pc = valid ? p : (P - 1);

        float4 pr = ((const float4*)priors)[pc];       // cxcywh
        float px0 = pr.x - 0.5f * pr.z, py0 = pr.y - 0.5f * pr.w;
        float px1 = pr.x + 0.5f * pr.z, py1 = pr.y + 0.5f * pr.w;
        float parea = pr.z * pr.w;

        unsigned bestA = 0u;
#pragma unroll
        for (int o = 0; o < O; o++) {
            float4 bx = sbox[o];
            float lx = fmaxf(bx.x, px0), ly = fmaxf(bx.y, py0);
            float hx = fminf(bx.z, px1), hy = fminf(bx.w, py1);
            float w = fmaxf(hx - lx, 0.0f), h = fmaxf(hy - ly, 0.0f);
            float inter = w * h;
            float ov = __fdividef(inter, sarea[o] + parea - inter);
            unsigned ob = __float_as_uint(ov);
            // per-prior argmax: mask 5 bits, embed (31-o) -> lowest o wins ties
            bestA = max(bestA, (ob & 0xFFFFFFE0u) | (unsigned)(31 - o));
            // per-object max: mask 7 bits, embed (3-batch)<<5 | (31-lane)
            unsigned keyB = valid
                ? ((ob & 0xFFFFFF80u) | (unsigned)((3 - batch) << 5) | (unsigned)(31 - lane))
                : 0u;
            unsigned m = __reduce_max_sync(0xFFFFFFFFu, keyB);
            if (lane == o) runB = max(runB, m);
        }
        if (valid) {
            int bo = 31 - (int)(bestA & 31u);
            float bov = __uint_as_float(bestA & 0xFFFFFFE0u);
            int tc = (bov < 0.5f) ? 0 : slab[bo];
            g_match[b * P + p] = (bo << 8) | tc;
        }
    }

    swkey[wid][lane] = runB;         // lane L = object L
    __syncthreads();

    if (tid < O) {                   // thread o: combine 16 warps
        int o = tid;
        unsigned long long best = 0ULL;
#pragma unroll
        for (int w = 0; w < 16; w++) {
            unsigned k = swkey[w][o];
            int batch = 3 - (int)((k >> 5) & 3u);
            int ln = 31 - (int)(k & 31u);
            unsigned p = (unsigned)(batch * BATCH_STRIDE + (blk * 16 + w) * 32 + ln);
            unsigned long long cand =
                ((unsigned long long)(k & 0xFFFFFF80u) << 32) | (0xFFFFFFFFu - p);
            if (cand > best) best = cand;
        }
        g_obj_slice[(b * NSLICE + blk) * O + o] = best;
    }
}

// ---------------- inline select (runs inside loss kernel) --------------------
struct SelShared {
    int hist[256];
    int ssum[256];
    int wtot[8];
    unsigned sprefix;
    int sK;
    float swsum[16];
};

__device__ void do_select(int b, SelShared* S, float* out) {
    int tid = threadIdx.x;
    const float* mined = g_mined + b * P;
    int np = g_num_pos[b];
    int K = min(3 * np, P - np);
    float result = 0.0f;

    if (K > 0) {
        if (tid == 0) { S->sprefix = 0u; S->sK = K; }
        __syncthreads();
        for (int shift = 24; shift >= 0; shift -= 8) {
            if (tid < 256) S->hist[tid] = 0;
            __syncthreads();
            unsigned prefix = S->sprefix;
            int Kr = S->sK;
            for (int p = tid; p < P; p += 512) {
                unsigned k = okey(mined[p]);
                if (shift == 24 || (k >> (shift + 8)) == prefix)
                    atomicAdd(&S->hist[(k >> shift) & 255u], 1);
            }
            __syncthreads();
            int v = 0;
            int w = tid >> 5, l = tid & 31;
            if (tid < 256) {                       // warp-level suffix scan
                v = S->hist[tid];
#pragma unroll
                for (int off = 1; off < 32; off <<= 1) {
                    int u = __shfl_down_sync(0xFFFFFFFFu, v, off);
                    if (l + off < 32) v += u;
                }
                if (l == 0) S->wtot[w] = v;
            }
            __syncthreads();
            if (tid < 256) {
                int add = 0;
#pragma unroll
                for (int g = 1; g < 8; g++) if (w + g < 8) add += S->wtot[w + g];
                S->ssum[tid] = v + add;
            }
            __syncthreads();
            if (tid < 256) {
                int mine = S->ssum[tid];
                int nxt = (tid < 255) ? S->ssum[tid + 1] : 0;
                if (mine >= Kr && nxt < Kr) {      // unique tid
                    S->sprefix = (prefix << 8) | (unsigned)tid;
                    S->sK = Kr - nxt;
                }
            }
            __syncthreads();
        }
        unsigned T = S->sprefix;
        int rr = S->sK;
        float Tval = fromkey(T);

        float sum = 0.0f;
        for (int p = tid; p < P; p += 512) {
            float v2 = mined[p];
            if (okey(v2) > T) sum += v2;
        }
#pragma unroll
        for (int off = 16; off; off >>= 1) sum += __shfl_xor_sync(0xFFFFFFFFu, sum, off);
        if ((tid & 31) == 0) S->swsum[tid >> 5] = sum;
        __syncthreads();
        if (tid == 0) {
            float tot = 0.0f;
#pragma unroll
            for (int i = 0; i < 16; i++) tot += S->swsum[i];
            result = tot + (float)rr * Tval;
        }
    } else {
        __syncthreads();
    }

    __shared__ int slastf;
    if (tid == 0) {
        g_neg_sum[b] = result;
        __threadfence();
        int d = atomicAdd(&g_done, 1);
        slastf = (d == B - 1);
    }
    __syncthreads();

    if (slastf) {                                  // very last batch: finalize
        __threadfence();
        float ns = 0.0f, npv = 0.0f;
        if (tid < B) {
            ns = *(volatile float*)&g_neg_sum[tid];
            npv = (float)*(volatile int*)&g_num_pos[tid];
        }
#pragma unroll
        for (int off = 16; off; off >>= 1) {
            ns += __shfl_xor_sync(0xFFFFFFFFu, ns, off);
            npv += __shfl_xor_sync(0xFFFFFFFFu, npv, off);
        }
        __shared__ float a2[2], c2[2];
        if (tid < B && (tid & 31) == 0) { a2[tid >> 5] = ns; c2[tid >> 5] = npv; }
        __syncthreads();
        if (tid == 0) {
            float totns = a2[0] + a2[1];
            float n = c2[0] + c2[1];
            out[0] = (g_pos_ce + totns) / n;
            out[1] = g_sl1 / n;
        }
    }
}

// ---------------- K2: losses + mining + inline per-batch select --------------
__global__ void __launch_bounds__(512) loss_kernel(const float* __restrict__ locs,
                            const float* __restrict__ scores,
                            const int*   __restrict__ labels,
                            const float* __restrict__ boxes,
                            const float* __restrict__ priors,
                            float* __restrict__ out) {
    __shared__ __align__(16) float sm[RPB * C];    // 41472 bytes, float4-accessed
    __shared__ unsigned spriorF[2][O];
    __shared__ int slabF[2][O];
    __shared__ SelShared S;
    __shared__ int strig[2];
    size_t row0 = (size_t)blockIdx.x * RPB;
    int b0 = (int)(row0 / P);

    if (threadIdx.x < 64) {                        // reduce slices -> forced priors
        int bi = threadIdx.x >> 5, o = threadIdx.x & 31;
        int bb = min(b0 + bi, B - 1);
        unsigned long long m = 0ULL;
#pragma unroll
        for (int s = 0; s < NSLICE; s++)
            m = max(m, g_obj_slice[(bb * NSLICE + s) * O + o]);
        spriorF[bi][o] = 0xFFFFFFFFu - (unsigned)(m & 0xFFFFFFFFu);
        slabF[bi][o] = labels[bb * O + o];
    }

    // stage 128 rows flat (row0 multiple of 128 -> byte offset 41472*blk, 16B ok)
    const float4* src = (const float4*)(scores + row0 * C);
    float4* dst = (float4*)sm;
    const int N4 = RPB * C / 4;                    // 2592
#pragma unroll 4
    for (int i = threadIdx.x; i < N4; i += 512) dst[i] = src[i];
    __syncthreads();

    int k = threadIdx.x >> 2;                      // local row
    int q = threadIdx.x & 3;                       // quarter
    const float* my = sm + k * C;

    // conflict-free class split: q handles j = 32g + 8q + e  (j < 81)
    float sa[4] = {0.f, 0.f, 0.f, 0.f};
#pragma unroll
    for (int it = 0; it < 24; it++) {
        int g = it >> 3, e = it & 7;
        int j = g * 32 + (q << 3) + e;
        if (j < C) sa[it & 3] += __expf(my[j]);
    }
    float sum = (sa[0] + sa[1]) + (sa[2] + sa[3]);
    sum += __shfl_xor_sync(0xFFFFFFFFu, sum, 1);   // quarters live in same warp
    sum += __shfl_xor_sync(0xFFFFFFFFu, sum, 2);
    float lse = __logf(sum);

    if (q == 0) {
        int r = (int)row0 + k;
        int b = r / P;
        int p = r - b * P;
        int bi = b - b0;

        int mm = g_match[r];
        int tc = mm & 0xFF;
        int obj = mm >> 8;
#pragma unroll
        for (int o = 0; o < O; o++) {              // ascending: last (highest o) wins
            if (spriorF[bi][o] == (unsigned)p) { tc = slabF[bi][o]; obj = o; }
        }

        float mined;
        if (tc > 0) {
            atomicAdd(&g_pos_ce, lse - my[tc]);
            atomicAdd(&g_num_pos[b], 1);
            float4 bx = ((const float4*)boxes)[b * O + obj];
            float4 pr = ((const float4*)priors)[p];
            float cx = 0.5f * (bx.x + bx.z), cy = 0.5f * (bx.y + bx.w);
            float w = bx.z - bx.x, h = bx.w - bx.y;
            float t0 = (cx - pr.x) * 10.0f / pr.z;
            float t1 = (cy - pr.y) * 10.0f / pr.w;
            float t2 = __logf(w / pr.z) * 5.0f;
            float t3 = __logf(h / pr.w) * 5.0f;
            float4 pl = ((const float4*)locs)[r];
            float sl = smoothl1(pl.x - t0) + smoothl1(pl.y - t1) +
                       smoothl1(pl.z - t2) + smoothl1(pl.w - t3);
            atomicAdd(&g_sl1, sl);
            mined = NEG_INF;
        } else {
            mined = lse - my[0];
        }
        g_mined[r] = mined;
    }
    // order EVERY thread's g_mined/atomic writes before this block's
    // row-completion increment (fence+bar cumulativity across blocks)
    __threadfence();
    __syncthreads();

    // row-completion accounting; completing block runs that batch's select
    if (threadIdx.x == 0) {
        strig[0] = -1; strig[1] = -1;
        int rend = (int)row0 + RPB;
        int bend0 = (b0 + 1) * P;
        int n0 = min(rend, bend0) - (int)row0;
        int c0 = atomicAdd(&g_row_done[b0], n0) + n0;
        if (c0 == P) strig[0] = b0;
        if (rend > bend0) {
            int b1 = b0 + 1;
            int n1 = rend - bend0;
            int c1 = atomicAdd(&g_row_done[b1], n1) + n1;
            if (c1 == P) strig[1] = b1;
        }
    }
    __syncthreads();

#pragma unroll
    for (int t = 0; t < 2; t++) {
        int bsel = strig[t];
        if (bsel >= 0) {
            __threadfence();
            do_select(bsel, &S, out);
            __syncthreads();
        }
    }
}

// ---------------- launch ------------------------------------------------------
extern "C" void kernel_launch(void* const* d_in, const int* in_sizes, int n_in,
                              void* d_out, int out_size) {
    const float* locs   = (const float*)d_in[0];   // [B,P,4]
    const float* scores = (const float*)d_in[1];   // [B,P,C]
    const float* boxes  = (const float*)d_in[2];   // [B,O,4] xy
    const int*   labels = (const int*)  d_in[3];   // [B,O]
    const float* priors = (const float*)d_in[4];   // [P,4] cxcywh
    float* out = (float*)d_out;

    match_kernel<<<dim3(NSLICE, B), 512>>>(boxes, labels, priors);
    loss_kernel<<<(B * P) / RPB, 512>>>(locs, scores, labels, boxes, priors, out);
}

// round 12
// speedup vs baseline: 1.9198x; 1.0194x over previous
#include <cuda_runtime.h>
#include <cuda_pipeline.h>
#include <cstdint>

#define B 64
#define P 8732
#define C 81
#define O 32
#define RPB 128            // rows per loss block (B*P = 558848 = 128*4366)
#define NSLICE 16          // match blocks per batch item
#define BATCH_STRIDE (NSLICE * 16 * 32)   // 8192 priors per warp-sweep

#define NEG_INF (__int_as_float(0xff800000))

// ---------------- scratch (device globals; no allocation anywhere) ----------
__device__ unsigned long long g_obj_slice[B * NSLICE * O]; // (ov_bits<<32)|~p
__device__ int   g_match[B * P];                 // packed (obj<<8)|tc per prior
__device__ float g_mined[B * P];                 // bg_loss (neg) / -inf (pos)
__device__ int   g_num_pos[B];
__device__ float g_neg_sum[B];
__device__ int   g_row_done[B];
__device__ float g_pos_ce;
__device__ float g_sl1;
__device__ int   g_done;

// ---------------- helpers ----------------------------------------------------
__device__ __forceinline__ unsigned okey(float f) {
    unsigned u = __float_as_uint(f);
    return (u & 0x80000000u) ? ~u : (u | 0x80000000u);
}
__device__ __forceinline__ float fromkey(unsigned k) {
    unsigned u = (k & 0x80000000u) ? (k & 0x7FFFFFFFu) : ~k;
    return __uint_as_float(u);
}
__device__ __forceinline__ float smoothl1(float d) {
    float a = fabsf(d);
    return (a < 1.0f) ? 0.5f * a * a : a - 0.5f;
}

// ---------------- K1: fused matching, single IoU pass ------------------------
__global__ void __launch_bounds__(512, 2) match_kernel(
        const float* __restrict__ boxes,
        const int*   __restrict__ labels,
        const float* __restrict__ priors) {
    int blk = blockIdx.x;            // 0..NSLICE-1
    int b = blockIdx.y;
    int tid = threadIdx.x;
    int wid = tid >> 5;              // 0..15
    int lane = tid & 31;
    __shared__ float4 sbox[O];
    __shared__ float  sarea[O];
    __shared__ int    slab[O];
    __shared__ unsigned swkey[16][O];    // per-warp per-object best key
    if (tid < O) {
        float4 bx = ((const float4*)boxes)[b * O + tid];
        sbox[tid] = bx;
        sarea[tid] = (bx.z - bx.x) * (bx.w - bx.y);
        slab[tid] = labels[b * O + tid];
    }
    if (blk == 0 && b == 0) {        // init accumulators for downstream launches
        if (tid < B) { g_num_pos[tid] = 0; g_neg_sum[tid] = 0.0f; g_row_done[tid] = 0; }
        if (tid == 0) { g_pos_ce = 0.0f; g_sl1 = 0.0f; g_done = 0; }
    }
    __syncthreads();

    int gwarp = blk * 16 + wid;      // 0..255 within this batch item
    unsigned runB = 0u;              // lane L holds object L's running best key

    for (int batch = 0; batch < 2; batch++) {
        int pbase = batch * BATCH_STRIDE + gwarp * 32;
        if (pbase >= P) break;
        int p = pbase + lane;
        bool valid = (p < P);
        int pc = valid ? p : (P - 1);

        float4 pr = ((const float4*)priors)[pc];       // cxcywh
        float px0 = pr.x - 0.5f * pr.z, py0 = pr.y - 0.5f * pr.w;
        float px1 = pr.x + 0.5f * pr.z, py1 = pr.y + 0.5f * pr.w;
        float parea = pr.z * pr.w;

        unsigned bestA = 0u;
#pragma unroll
        for (int o = 0; o < O; o++) {
            float4 bx = sbox[o];
            float lx = fmaxf(bx.x, px0), ly = fmaxf(bx.y, py0);
            float hx = fminf(bx.z, px1), hy = fminf(bx.w, py1);
            float w = fmaxf(hx - lx, 0.0f), h = fmaxf(hy - ly, 0.0f);
            float inter = w * h;
            float ov = __fdividef(inter, sarea[o] + parea - inter);
            unsigned ob = __float_as_uint(ov);
            // per-prior argmax: mask 5 bits, embed (31-o) -> lowest o wins ties
            bestA = max(bestA, (ob & 0xFFFFFFE0u) | (unsigned)(31 - o));
            // per-object max: mask 7 bits, embed (3-batch)<<5 | (31-lane)
            unsigned keyB = valid
                ? ((ob & 0xFFFFFF80u) | (unsigned)((3 - batch) << 5) | (unsigned)(31 - lane))
                : 0u;
            unsigned m = __reduce_max_sync(0xFFFFFFFFu, keyB);
            if (lane == o) runB = max(runB, m);
        }
        if (valid) {
            int bo = 31 - (int)(bestA & 31u);
            float bov = __uint_as_float(bestA & 0xFFFFFFE0u);
            int tc = (bov < 0.5f) ? 0 : slab[bo];
            g_match[b * P + p] = (bo << 8) | tc;
        }
    }

    swkey[wid][lane] = runB;         // lane L = object L
    __syncthreads();

    if (tid < O) {                   // thread o: combine 16 warps
        int o = tid;
        unsigned long long best = 0ULL;
#pragma unroll
        for (int w = 0; w < 16; w++) {
            unsigned k = swkey[w][o];
            int batch = 3 - (int)((k >> 5) & 3u);
            int ln = 31 - (int)(k & 31u);
            unsigned p = (unsigned)(batch * BATCH_STRIDE + (blk * 16 + w) * 32 + ln);
            unsigned long long cand =
                ((unsigned long long)(k & 0xFFFFFF80u) << 32) | (0xFFFFFFFFu - p);
            if (cand > best) best = cand;
        }
        g_obj_slice[(b * NSLICE + blk) * O + o] = best;
    }
}

// ---------------- inline select (runs inside loss kernel) --------------------
struct SelShared {
    int hist[256];
    int ssum[256];
    int wtot[8];
    unsigned sprefix;
    int sK;
    float swsum[16];
};

__device__ void do_select(int b, SelShared* S, float* out) {
    int tid = threadIdx.x;
    const float* mined = g_mined + b * P;
    int np = g_num_pos[b];
    int K = min(3 * np, P - np);
    float result = 0.0f;

    if (K > 0) {
        if (tid == 0) { S->sprefix = 0u; S->sK = K; }
        __syncthreads();
        for (int shift = 24; shift >= 0; shift -= 8) {
            if (tid < 256) S->hist[tid] = 0;
            __syncthreads();
            unsigned prefix = S->sprefix;
            int Kr = S->sK;
            for (int p = tid; p < P; p += 512) {
                unsigned k = okey(mined[p]);
                if (shift == 24 || (k >> (shift + 8)) == prefix)
                    atomicAdd(&S->hist[(k >> shift) & 255u], 1);
            }
            __syncthreads();
            int v = 0;
            int w = tid >> 5, l = tid & 31;
            if (tid < 256) {                       // warp-level suffix scan
                v = S->hist[tid];
#pragma unroll
                for (int off = 1; off < 32; off <<= 1) {
                    int u = __shfl_down_sync(0xFFFFFFFFu, v, off);
                    if (l + off < 32) v += u;
                }
                if (l == 0) S->wtot[w] = v;
            }
            __syncthreads();
            if (tid < 256) {
                int add = 0;
#pragma unroll
                for (int g = 1; g < 8; g++) if (w + g < 8) add += S->wtot[w + g];
                S->ssum[tid] = v + add;
            }
            __syncthreads();
            if (tid < 256) {
                int mine = S->ssum[tid];
                int nxt = (tid < 255) ? S->ssum[tid + 1] : 0;
                if (mine >= Kr && nxt < Kr) {      // unique tid
                    S->sprefix = (prefix << 8) | (unsigned)tid;
                    S->sK = Kr - nxt;
                }
            }
            __syncthreads();
        }
        unsigned T = S->sprefix;
        int rr = S->sK;
        float Tval = fromkey(T);

        float sum = 0.0f;
        for (int p = tid; p < P; p += 512) {
            float v2 = mined[p];
            if (okey(v2) > T) sum += v2;
        }
#pragma unroll
        for (int off = 16; off; off >>= 1) sum += __shfl_xor_sync(0xFFFFFFFFu, sum, off);
        if ((tid & 31) == 0) S->swsum[tid >> 5] = sum;
        __syncthreads();
        if (tid == 0) {
            float tot = 0.0f;
#pragma unroll
            for (int i = 0; i < 16; i++) tot += S->swsum[i];
            result = tot + (float)rr * Tval;
        }
    } else {
        __syncthreads();
    }

    __shared__ int slastf;
    if (tid == 0) {
        g_neg_sum[b] = result;
        __threadfence();
        int d = atomicAdd(&g_done, 1);
        slastf = (d == B - 1);
    }
    __syncthreads();

    if (slastf) {                                  // very last batch: finalize
        __threadfence();
        float ns = 0.0f, npv = 0.0f;
        if (tid < B) {
            ns = *(volatile float*)&g_neg_sum[tid];
            npv = (float)*(volatile int*)&g_num_pos[tid];
        }
#pragma unroll
        for (int off = 16; off; off >>= 1) {
            ns += __shfl_xor_sync(0xFFFFFFFFu, ns, off);
            npv += __shfl_xor_sync(0xFFFFFFFFu, npv, off);
        }
        __shared__ float a2[2], c2[2];
        if (tid < B && (tid & 31) == 0) { a2[tid >> 5] = ns; c2[tid >> 5] = npv; }
        __syncthreads();
        if (tid == 0) {
            float totns = a2[0] + a2[1];
            float n = c2[0] + c2[1];
            out[0] = (g_pos_ce + totns) / n;
            out[1] = g_sl1 / n;
        }
    }
}

// ---------------- K2: losses, warp-self-contained cp.async staging -----------
__global__ void __launch_bounds__(512) loss_kernel(const float* __restrict__ locs,
                            const float* __restrict__ scores,
                            const int*   __restrict__ labels,
                            const float* __restrict__ boxes,
                            const float* __restrict__ priors,
                            float* __restrict__ out) {
    __shared__ __align__(16) float sm[RPB * C];    // 41472 bytes
    __shared__ __align__(16) int smatch[RPB];
    __shared__ unsigned spriorF[2][O];
    __shared__ int slabF[2][O];
    __shared__ SelShared S;
    __shared__ int strig[2];
    int tid = threadIdx.x;
    int wid = tid >> 5;                            // warp 0..15, owns rows [8w,8w+8)
    int lane = tid & 31;
    size_t row0 = (size_t)blockIdx.x * RPB;
    int b0 = (int)(row0 / P);

    // ---- async stage: warp w copies its own 8 rows (2592B) + its 8 match ints
    {
        const char* gsrc = (const char*)(scores + (row0 + wid * 8) * C);
        char* sdst = (char*)(sm + wid * 8 * C);
#pragma unroll
        for (int i = lane; i < 162; i += 32)       // 162 x 16B = 2592B
            __pipeline_memcpy_async(sdst + i * 16, gsrc + i * 16, 16);
        if (lane < 2)                              // 8 ints = 2 x 16B
            __pipeline_memcpy_async((char*)(smatch + wid * 8) + lane * 16,
                                    (const char*)(g_match + row0 + wid * 8) + lane * 16, 16);
        __pipeline_commit();
    }

    // overlap: forced-prior reduction while copies fly
    if (tid < 64) {
        int bi = tid >> 5, o = tid & 31;
        int bb = min(b0 + bi, B - 1);
        unsigned long long m = 0ULL;
#pragma unroll
        for (int s = 0; s < NSLICE; s++)
            m = max(m, g_obj_slice[(bb * NSLICE + s) * O + o]);
        spriorF[bi][o] = 0xFFFFFFFFu - (unsigned)(m & 0xFFFFFFFFu);
        slabF[bi][o] = labels[bb * O + o];
    }
    __syncthreads();                               // publish spriorF (does not drain async)

    __pipeline_wait_prior(0);                      // my lane's copies done
    __syncwarp();                                  // whole warp's copies visible

    int k = tid >> 2;                              // local row (within warp's 8)
    int q = tid & 3;                               // quarter
    const float* my = sm + k * C;

    // conflict-free class split: q handles j = 32g + 8q + e  (j < 81)
    float sa[4] = {0.f, 0.f, 0.f, 0.f};
#pragma unroll
    for (int it = 0; it < 24; it++) {
        int g = it >> 3, e = it & 7;
        int j = g * 32 + (q << 3) + e;
        if (j < C) sa[it & 3] += __expf(my[j]);
    }
    float sum = (sa[0] + sa[1]) + (sa[2] + sa[3]);
    sum += __shfl_xor_sync(0xFFFFFFFFu, sum, 1);   // quarters live in same warp
    sum += __shfl_xor_sync(0xFFFFFFFFu, sum, 2);
    float lse = __logf(sum);

    if (q == 0) {
        int r = (int)row0 + k;
        int b = r / P;
        int p = r - b * P;
        int bi = b - b0;

        int mm = smatch[k];
        int tc = mm & 0xFF;
        int obj = mm >> 8;
#pragma unroll
        for (int o = 0; o < O; o++) {              // ascending: last (highest o) wins
            if (spriorF[bi][o] == (unsigned)p) { tc = slabF[bi][o]; obj = o; }
        }

        float mined;
        if (tc > 0) {
            atomicAdd(&g_pos_ce, lse - my[tc]);
            atomicAdd(&g_num_pos[b], 1);
            float4 bx = ((const float4*)boxes)[b * O + obj];
            float4 pr = ((const float4*)priors)[p];
            float cx = 0.5f * (bx.x + bx.z), cy = 0.5f * (bx.y + bx.w);
            float w = bx.z - bx.x, h = bx.w - bx.y;
            float t0 = (cx - pr.x) * 10.0f / pr.z;
            float t1 = (cy - pr.y) * 10.0f / pr.w;
            float t2 = __logf(w / pr.z) * 5.0f;
            float t3 = __logf(h / pr.w) * 5.0f;
            float4 pl = ((const float4*)locs)[r];
            float sl = smoothl1(pl.x - t0) + smoothl1(pl.y - t1) +
                       smoothl1(pl.z - t2) + smoothl1(pl.w - t3);
            atomicAdd(&g_sl1, sl);
            mined = NEG_INF;
        } else {
            mined = lse - my[0];
        }
        g_mined[r] = mined;
    }
    // order EVERY thread's g_mined/atomic writes before this block's
    // row-completion increment (fence+bar cumulativity across blocks)
    __threadfence();
    __syncthreads();

    // row-completion accounting; completing block runs that batch's select
    if (tid == 0) {
        strig[0] = -1; strig[1] = -1;
        int rend = (int)row0 + RPB;
        int bend0 = (b0 + 1) * P;
        int n0 = min(rend, bend0) - (int)row0;
        int c0 = atomicAdd(&g_row_done[b0], n0) + n0;
        if (c0 == P) strig[0] = b0;
        if (rend > bend0) {
            int b1 = b0 + 1;
            int n1 = rend - bend0;
            int c1 = atomicAdd(&g_row_done[b1], n1) + n1;
            if (c1 == P) strig[1] = b1;
        }
    }
    __syncthreads();

#pragma unroll
    for (int t = 0; t < 2; t++) {
        int bsel = strig[t];
        if (bsel >= 0) {
            __threadfence();
            do_select(bsel, &S, out);
            __syncthreads();
        }
    }
}

// ---------------- launch ------------------------------------------------------
extern "C" void kernel_launch(void* const* d_in, const int* in_sizes, int n_in,
                              void* d_out, int out_size) {
    const float* locs   = (const float*)d_in[0];   // [B,P,4]
    const float* scores = (const float*)d_in[1];   // [B,P,C]
    const float* boxes  = (const float*)d_in[2];   // [B,O,4] xy
    const int*   labels = (const int*)  d_in[3];   // [B,O]
    const float* priors = (const float*)d_in[4];   // [P,4] cxcywh
    float* out = (float*)d_out;

    match_kernel<<<dim3(NSLICE, B), 512>>>(boxes, labels, priors);
    loss_kernel<<<(B * P) / RPB, 512>>>(locs, scores, labels, boxes, priors, out);
}